// round 4
// baseline (speedup 1.0000x reference)
#include <cuda_runtime.h>
#include <math.h>
#include <stdint.h>

#define B_ 32
#define T_ 1024
#define D_ 512
#define H_ 2048
#define E_ 8

#define BM 128
#define BN 256
#define BK 32
#define STAGES 3

#define RSTR 40                               // floats per smem row (32 data + 8 pad)
#define A_BYTES (BM * RSTR * 4)               // 20480
#define B_BYTES (BN * RSTR * 4)               // 40960
#define STAGE_BYTES (A_BYTES + B_BYTES)       // 61440
#define SMEMSZ (STAGES * STAGE_BYTES)         // 184320

// ---------------------------------------------------------------------------
// scratch (device globals — no allocation allowed)
// ---------------------------------------------------------------------------
__device__ int   g_eidx[B_][2];
__device__ float g_prob[B_][2];
__device__ float g_pool[B_][8][D_];
__device__ float g_xc[(size_t)B_ * T_ * D_];        // tf32-RNA x, k-permuted cols
__device__ float g_w1t[(size_t)E_ * H_ * D_];       // w1^T [E][H][D'], RNA, k-permuted
__device__ float g_w2t[(size_t)E_ * D_ * H_];       // w2^T [E][D][H'], RNA, k-permuted
__device__ float g_h[(size_t)B_ * T_ * (2 * H_)];   // p*silu(...), RNA, k-permuted

// k-permutation within each 8-group: pos(k) = (k%4)*2 + k/4
__device__ __host__ __forceinline__ int kperm(int k) {
    return (k & ~7) | (((k & 3) << 1) | ((k >> 2) & 1));
}

// ---------------------------------------------------------------------------
// helpers
// ---------------------------------------------------------------------------
__device__ __forceinline__ unsigned f2tf32(float f) {
    unsigned u;
    asm("cvt.rna.tf32.f32 %0, %1;" : "=r"(u) : "f"(f));
    return u;
}
__device__ __forceinline__ float rna32(float f) { return __uint_as_float(f2tf32(f)); }

__device__ __forceinline__ uint32_t smem_u32(const void* p) {
    uint32_t a;
    asm("{ .reg .u64 t; cvta.to.shared.u64 t, %1; cvt.u32.u64 %0, t; }" : "=r"(a) : "l"(p));
    return a;
}
__device__ __forceinline__ void cp16(uint32_t dst, const void* src) {
    asm volatile("cp.async.cg.shared.global [%0], [%1], 16;" :: "r"(dst), "l"(src));
}
__device__ __forceinline__ void cp_commit() {
    asm volatile("cp.async.commit_group;" ::: "memory");
}
template <int N>
__device__ __forceinline__ void cp_wait() {
    asm volatile("cp.async.wait_group %0;" :: "n"(N) : "memory");
}

__device__ __forceinline__ void mma_tf32(float* d, const unsigned* a, const unsigned* b) {
    asm volatile(
        "mma.sync.aligned.m16n8k8.row.col.f32.tf32.tf32.f32 "
        "{%0,%1,%2,%3}, {%4,%5,%6,%7}, {%8,%9}, {%0,%1,%2,%3};\n"
        : "+f"(d[0]), "+f"(d[1]), "+f"(d[2]), "+f"(d[3])
        : "r"(a[0]), "r"(a[1]), "r"(a[2]), "r"(a[3]), "r"(b[0]), "r"(b[1]));
}

// ---------------------------------------------------------------------------
// prep kernels
// ---------------------------------------------------------------------------
// pooling partials + tf32-rounded, k-permuted copy of x
__global__ void pool_convert_kernel(const float* __restrict__ x) {
    const int b = blockIdx.x, ch = blockIdx.y, d = threadIdx.x;   // 512 threads
    const int dp = kperm(d);
    const size_t rbase = ((size_t)b * T_ + (size_t)ch * 128) * D_;
    float s = 0.f;
    for (int t = 0; t < 128; t++) {
        float v = x[rbase + (size_t)t * D_ + d];
        s += v;
        g_xc[rbase + (size_t)t * D_ + dp] = rna32(v);
    }
    g_pool[b][ch][d] = s;
}

// tiled transpose + RNA + inner-dim k-permute: src [E][R][C] -> dst [E][C][perm(R)]
__global__ void transpose_rc_kernel(const float* __restrict__ src, float* __restrict__ dst,
                                    int R, int C) {
    __shared__ float tile[32][33];
    const int e = blockIdx.z;
    const float* S = src + (size_t)e * R * C;
    float* Dp = dst + (size_t)e * R * C;
    const int c0 = blockIdx.x * 32, r0 = blockIdx.y * 32;
    const int tx = threadIdx.x, ty = threadIdx.y;
    #pragma unroll
    for (int i = 0; i < 4; i++)
        tile[ty + i * 8][tx] = S[(size_t)(r0 + ty + i * 8) * C + c0 + tx];
    __syncthreads();
    #pragma unroll
    for (int i = 0; i < 4; i++)
        Dp[(size_t)(c0 + ty + i * 8) * R + r0 + kperm(tx)] = rna32(tile[tx][ty + i * 8]);
}

// finish gating: logits, top-2, softmax
__global__ void gate_kernel(const float* __restrict__ gw, const float* __restrict__ gb,
                            float* __restrict__ out_logits) {
    __shared__ float pooled[D_];
    __shared__ float logits[E_];
    const int b = blockIdx.x, d = threadIdx.x;
    float s = 0.f;
    #pragma unroll
    for (int c = 0; c < 8; c++) s += g_pool[b][c][d];
    pooled[d] = s * (1.0f / (float)T_);
    __syncthreads();
    const int w = threadIdx.x >> 5, lane = threadIdx.x & 31;
    if (w < E_) {
        float acc = 0.f;
        for (int j = lane; j < D_; j += 32) acc += pooled[j] * gw[(size_t)j * E_ + w];
        #pragma unroll
        for (int o = 16; o > 0; o >>= 1) acc += __shfl_xor_sync(0xffffffffu, acc, o);
        if (lane == 0) logits[w] = acc + gb[w];
    }
    __syncthreads();
    if (threadIdx.x == 0) {
        int i0 = 0; float l0 = logits[0];
        for (int e = 1; e < E_; e++) if (logits[e] > l0) { l0 = logits[e]; i0 = e; }
        int i1 = -1; float l1 = -1e30f;
        for (int e = 0; e < E_; e++) if (e != i0 && logits[e] > l1) { l1 = logits[e]; i1 = e; }
        float e1 = expf(l1 - l0);
        float inv = 1.0f / (1.0f + e1);
        g_eidx[b][0] = i0; g_eidx[b][1] = i1;
        g_prob[b][0] = inv; g_prob[b][1] = e1 * inv;
        for (int e = 0; e < E_; e++) out_logits[b * E_ + e] = logits[e];
    }
}

// ---------------------------------------------------------------------------
// GEMM core (shared): 256 threads, 8 warps 2(m)x4(n), warp tile 64x64
// A smem [BM][RSTR] row-major (k inner, permuted); B smem [BN][RSTR] (k inner)
// ---------------------------------------------------------------------------

#define ISSUE_STAGE(slot, A_SRC, B_SRC) do {                                   \
    const uint32_t _as = sm_base + (slot) * STAGE_BYTES;                       \
    const uint32_t _bs = _as + A_BYTES;                                        \
    _Pragma("unroll")                                                          \
    for (int _i = 0; _i < 4; _i++) {                                           \
        const int _c = _i * 256 + tid;                                         \
        const int _r = _c >> 3, _cc = _c & 7;                                  \
        cp16(_as + _r * (RSTR * 4) + _cc * 16, (A_SRC(_r, _cc)));              \
    }                                                                          \
    _Pragma("unroll")                                                          \
    for (int _i = 0; _i < 8; _i++) {                                           \
        const int _c = _i * 256 + tid;                                         \
        const int _r = _c >> 3, _cc = _c & 7;                                  \
        cp16(_bs + _r * (RSTR * 4) + _cc * 16, (B_SRC(_r, _cc)));              \
    }                                                                          \
} while (0)

#define COMPUTE_STAGE(slot) do {                                               \
    const float2* _A = (const float2*)(smem + (slot) * STAGE_BYTES);           \
    const float2* _B = (const float2*)(smem + (slot) * STAGE_BYTES + A_BYTES); \
    _Pragma("unroll")                                                          \
    for (int ks = 0; ks < 4; ks++) {                                           \
        unsigned af[4][4], bf[8][2];                                           \
        _Pragma("unroll")                                                      \
        for (int mt = 0; mt < 4; mt++) {                                       \
            const int m = wm + mt * 16 + g;                                    \
            const float2 r0 = _A[m * 20 + ks * 4 + t4];                        \
            const float2 r1 = _A[(m + 8) * 20 + ks * 4 + t4];                  \
            af[mt][0] = __float_as_uint(r0.x); af[mt][1] = __float_as_uint(r1.x); \
            af[mt][2] = __float_as_uint(r0.y); af[mt][3] = __float_as_uint(r1.y); \
        }                                                                      \
        _Pragma("unroll")                                                      \
        for (int nt = 0; nt < 8; nt++) {                                       \
            const int n = wn + nt * 8 + g;                                     \
            const float2 v = _B[n * 20 + ks * 4 + t4];                         \
            bf[nt][0] = __float_as_uint(v.x); bf[nt][1] = __float_as_uint(v.y); \
        }                                                                      \
        _Pragma("unroll")                                                      \
        for (int mt = 0; mt < 4; mt++)                                         \
            _Pragma("unroll")                                                  \
            for (int nt = 0; nt < 8; nt++)                                     \
                mma_tf32(acc[mt][nt], af[mt], bf[nt]);                         \
    }                                                                          \
} while (0)

// ---------------------------------------------------------------------------
// GEMM1: h[b][t][slot*H + perm(n)] = rna( p * silu( xc[b] @ w1t[e]^T + b1[e] ) )
// A: g_xc[b] [T, D'];  B: g_w1t[e] [H, D']  (both k=D inner, permuted)
// grid (H/BN=8, T/BM=8, B*2=64)
// ---------------------------------------------------------------------------
__global__ __launch_bounds__(256, 1) void gemm1_kernel(const float* __restrict__ b1) {
    extern __shared__ char smem[];
    const uint32_t sm_base = smem_u32(smem);

    const int bz = blockIdx.z, b = bz >> 1, slot = bz & 1;
    const int e = g_eidx[b][slot];
    const float p = g_prob[b][slot];
    const int m0 = blockIdx.y * BM;
    const int n0 = blockIdx.x * BN;
    const int tid  = threadIdx.x;
    const int warp = tid >> 5, lane = tid & 31;
    const int g = lane >> 2, t4 = lane & 3;
    const int wm = (warp & 1) * 64;
    const int wn = (warp >> 1) * 64;

    const float* Ag = g_xc  + ((size_t)b * T_ + m0) * D_;
    const float* Bg = g_w1t + ((size_t)e * H_ + n0) * D_;

    float acc[4][8][4];
    #pragma unroll
    for (int i = 0; i < 4; i++)
        #pragma unroll
        for (int j = 0; j < 8; j++)
            #pragma unroll
            for (int r = 0; r < 4; r++) acc[i][j][r] = 0.f;

    const int NK = D_ / BK;   // 16
    #define A1(r, c) (Ag + (size_t)(r) * D_ + kk * BK + (c) * 4)
    #define B1(r, c) (Bg + (size_t)(r) * D_ + kk * BK + (c) * 4)

    #pragma unroll
    for (int s = 0; s < STAGES - 1; s++) {
        const int kk = s;
        ISSUE_STAGE(s, A1, B1);
        cp_commit();
    }

    for (int kt = 0; kt < NK; kt++) {
        cp_wait<STAGES - 2>();
        __syncthreads();
        const int pf = kt + STAGES - 1;
        if (pf < NK) {
            const int kk = pf;
            ISSUE_STAGE(pf % STAGES, A1, B1);
        }
        cp_commit();
        COMPUTE_STAGE(kt % STAGES);
    }
    #undef A1
    #undef B1

    // epilogue: +b1, silu, *p, rna, write k-permuted (h is gemm2's K dim)
    const float* brow = b1 + (size_t)e * H_ + n0;
    float* Hb = g_h + ((size_t)b * T_ + m0) * (2 * H_) + (size_t)slot * H_ + n0;
    const int sp0 = ((2 * t4) & 3) * 2 + ((2 * t4) >> 2);   // perm of col%8
    #pragma unroll
    for (int mt = 0; mt < 4; mt++) {
        #pragma unroll
        for (int nt = 0; nt < 8; nt++) {
            #pragma unroll
            for (int half = 0; half < 2; half++) {
                const int row = wm + mt * 16 + g + half * 8;
                const int col = wn + nt * 8 + t4 * 2;
                float v0 = acc[mt][nt][half * 2 + 0] + brow[col];
                float v1 = acc[mt][nt][half * 2 + 1] + brow[col + 1];
                v0 = rna32(p * v0 * (1.0f / (1.0f + __expf(-v0))));
                v1 = rna32(p * v1 * (1.0f / (1.0f + __expf(-v1))));
                float* dst = Hb + (size_t)row * (2 * H_) + (col & ~7);
                dst[sp0]     = v0;
                dst[sp0 + 2] = v1;
            }
        }
    }
}

// ---------------------------------------------------------------------------
// GEMM2: out[b] = h_cat[b] @ [w2t[e0]; w2t[e1]]^T + p0*b2[e0] + p1*b2[e1] + x[b]
// A: g_h[b] [T, 2H'] (k inner, permuted);  B: g_w2t[e] [D, H'] (k inner, permuted)
// grid (D/BN=2, T/BM=8, B=32)
// ---------------------------------------------------------------------------
__global__ __launch_bounds__(256, 1) void gemm2_kernel(const float* __restrict__ x,
                                                       const float* __restrict__ b2,
                                                       float* __restrict__ out) {
    extern __shared__ char smem[];
    const uint32_t sm_base = smem_u32(smem);

    const int b = blockIdx.z;
    const int e0 = g_eidx[b][0], e1 = g_eidx[b][1];
    const float p0 = g_prob[b][0], p1 = g_prob[b][1];
    const int m0 = blockIdx.y * BM;
    const int n0 = blockIdx.x * BN;
    const int tid  = threadIdx.x;
    const int warp = tid >> 5, lane = tid & 31;
    const int g = lane >> 2, t4 = lane & 3;
    const int wm = (warp & 1) * 64;
    const int wn = (warp >> 1) * 64;

    const float* Ag  = g_h + ((size_t)b * T_ + m0) * (2 * H_);
    const float* Bg0 = g_w2t + ((size_t)e0 * D_ + n0) * H_;
    const float* Bg1 = g_w2t + ((size_t)e1 * D_ + n0) * H_;

    float acc[4][8][4];
    #pragma unroll
    for (int i = 0; i < 4; i++)
        #pragma unroll
        for (int j = 0; j < 8; j++)
            #pragma unroll
            for (int r = 0; r < 4; r++) acc[i][j][r] = 0.f;

    const int NK = (2 * H_) / BK;   // 128
    #define A2(r, c) (Ag + (size_t)(r) * (2 * H_) + kk * BK + (c) * 4)
    #define B2(r, c) ((kk < 64 ? Bg0 : Bg1) + (size_t)(r) * H_ + (kk & 63) * BK + (c) * 4)

    #pragma unroll
    for (int s = 0; s < STAGES - 1; s++) {
        const int kk = s;
        ISSUE_STAGE(s, A2, B2);
        cp_commit();
    }

    for (int kt = 0; kt < NK; kt++) {
        cp_wait<STAGES - 2>();
        __syncthreads();
        const int pf = kt + STAGES - 1;
        if (pf < NK) {
            const int kk = pf;
            ISSUE_STAGE(pf % STAGES, A2, B2);
        }
        cp_commit();
        COMPUTE_STAGE(kt % STAGES);
    }
    #undef A2
    #undef B2

    // epilogue: + p0*b2[e0] + p1*b2[e1] + x, write out (normal layout)
    const float* b2r0 = b2 + (size_t)e0 * D_ + n0;
    const float* b2r1 = b2 + (size_t)e1 * D_ + n0;
    const float* xb = x   + ((size_t)b * T_ + m0) * D_ + n0;
    float*       ob = out + ((size_t)b * T_ + m0) * D_ + n0;
    #pragma unroll
    for (int mt = 0; mt < 4; mt++) {
        #pragma unroll
        for (int nt = 0; nt < 8; nt++) {
            #pragma unroll
            for (int half = 0; half < 2; half++) {
                const int row = wm + mt * 16 + g + half * 8;
                const int col = wn + nt * 8 + t4 * 2;
                const float bias0 = p0 * b2r0[col]     + p1 * b2r1[col];
                const float bias1 = p0 * b2r0[col + 1] + p1 * b2r1[col + 1];
                const float2 xv = *(const float2*)&xb[(size_t)row * D_ + col];
                float v0 = acc[mt][nt][half * 2 + 0] + bias0 + xv.x;
                float v1 = acc[mt][nt][half * 2 + 1] + bias1 + xv.y;
                *(float2*)&ob[(size_t)row * D_ + col] = make_float2(v0, v1);
            }
        }
    }
}

// ---------------------------------------------------------------------------
extern "C" void kernel_launch(void* const* d_in, const int* in_sizes, int n_in,
                              void* d_out, int out_size) {
    const float* x  = (const float*)d_in[0];
    const float* gw = (const float*)d_in[1];
    const float* gb = (const float*)d_in[2];
    const float* w1 = (const float*)d_in[3];
    const float* b1 = (const float*)d_in[4];
    const float* w2 = (const float*)d_in[5];
    const float* b2 = (const float*)d_in[6];

    float* out = (float*)d_out;
    float* out_logits = out + (size_t)B_ * T_ * D_;

    cudaFuncSetAttribute(gemm1_kernel, cudaFuncAttributeMaxDynamicSharedMemorySize, SMEMSZ);
    cudaFuncSetAttribute(gemm2_kernel, cudaFuncAttributeMaxDynamicSharedMemorySize, SMEMSZ);

    // prep: pooling + RNA/permute/transpose copies
    pool_convert_kernel<<<dim3(B_, 8), 512>>>(x);
    {
        float* w1t_ptr; cudaGetSymbolAddress((void**)&w1t_ptr, g_w1t);
        float* w2t_ptr; cudaGetSymbolAddress((void**)&w2t_ptr, g_w2t);
        // w1 [E][D][H] -> w1t [E][H][perm(D)]
        transpose_rc_kernel<<<dim3(H_ / 32, D_ / 32, E_), dim3(32, 8)>>>(w1, w1t_ptr, D_, H_);
        // w2 [E][H][D] -> w2t [E][D][perm(H)]
        transpose_rc_kernel<<<dim3(D_ / 32, H_ / 32, E_), dim3(32, 8)>>>(w2, w2t_ptr, H_, D_);
    }
    gate_kernel<<<B_, 512>>>(gw, gb, out_logits);

    gemm1_kernel<<<dim3(H_ / BN, T_ / BM, B_ * 2), 256, SMEMSZ>>>(b1);
    gemm2_kernel<<<dim3(D_ / BN, T_ / BM, B_), 256, SMEMSZ>>>(x, b2, out);
}

// round 5
// speedup vs baseline: 1.7500x; 1.7500x over previous
#include <cuda_runtime.h>
#include <cuda_fp16.h>
#include <math.h>
#include <stdint.h>

#define B_ 32
#define T_ 1024
#define D_ 512
#define H_ 2048
#define E_ 8

#define BM 128
#define BN 128
#define BK 32                    // halves per k-tile (2 x k16 mma steps)
#define STAGES 4

#define RSTR 40                               // halves per smem row (32 data + 8 pad)
#define A_BYTES (BM * RSTR * 2)               // 10240
#define B_BYTES (BN * RSTR * 2)               // 10240
#define STAGE_BYTES (A_BYTES + B_BYTES)       // 20480
#define SMEMSZ (STAGES * STAGE_BYTES)         // 81920

// ---------------------------------------------------------------------------
// scratch (device globals — no allocation allowed)
// ---------------------------------------------------------------------------
__device__ int    g_eidx[B_][2];
__device__ float  g_prob[B_][2];
__device__ float  g_pool[B_][8][D_];
__device__ __half g_xh[(size_t)B_ * T_ * D_];        // fp16 x
__device__ __half g_w1t[(size_t)E_ * H_ * D_];       // w1^T [E][H][D] fp16
__device__ __half g_w2t[(size_t)E_ * D_ * H_];       // w2^T [E][D][H] fp16
__device__ __half g_h[(size_t)B_ * T_ * (2 * H_)];   // p*silu(x@w1+b1) fp16

// ---------------------------------------------------------------------------
// helpers
// ---------------------------------------------------------------------------
__device__ __forceinline__ uint32_t smem_u32(const void* p) {
    uint32_t a;
    asm("{ .reg .u64 t; cvta.to.shared.u64 t, %1; cvt.u32.u64 %0, t; }" : "=r"(a) : "l"(p));
    return a;
}
__device__ __forceinline__ void cp16(uint32_t dst, const void* src) {
    asm volatile("cp.async.cg.shared.global [%0], [%1], 16;" :: "r"(dst), "l"(src));
}
__device__ __forceinline__ void cp_commit() {
    asm volatile("cp.async.commit_group;" ::: "memory");
}
template <int N>
__device__ __forceinline__ void cp_wait() {
    asm volatile("cp.async.wait_group %0;" :: "n"(N) : "memory");
}

__device__ __forceinline__ void mma_f16(float* d, const unsigned* a, const unsigned* b) {
    asm volatile(
        "mma.sync.aligned.m16n8k16.row.col.f32.f16.f16.f32 "
        "{%0,%1,%2,%3}, {%4,%5,%6,%7}, {%8,%9}, {%0,%1,%2,%3};\n"
        : "+f"(d[0]), "+f"(d[1]), "+f"(d[2]), "+f"(d[3])
        : "r"(a[0]), "r"(a[1]), "r"(a[2]), "r"(a[3]), "r"(b[0]), "r"(b[1]));
}

// ---------------------------------------------------------------------------
// prep kernels
// ---------------------------------------------------------------------------
// pooling partials + fp16 copy of x
__global__ void pool_convert_kernel(const float* __restrict__ x) {
    const int b = blockIdx.x, ch = blockIdx.y, d = threadIdx.x;   // 512 threads
    const size_t base = ((size_t)b * T_ + (size_t)ch * 128) * D_ + d;
    float s = 0.f;
    for (int t = 0; t < 128; t++) {
        float v = x[base + (size_t)t * D_];
        s += v;
        g_xh[base + (size_t)t * D_] = __float2half_rn(v);
    }
    g_pool[b][ch][d] = s;
}

// tiled transpose + fp16: src [E][R][C] float -> dst [E][C][R] half
__global__ void transpose_rc_kernel(const float* __restrict__ src, __half* __restrict__ dst,
                                    int R, int C) {
    __shared__ float tile[32][33];
    const int e = blockIdx.z;
    const float* S = src + (size_t)e * R * C;
    __half* Dp = dst + (size_t)e * R * C;
    const int c0 = blockIdx.x * 32, r0 = blockIdx.y * 32;
    const int tx = threadIdx.x, ty = threadIdx.y;
    #pragma unroll
    for (int i = 0; i < 4; i++)
        tile[ty + i * 8][tx] = S[(size_t)(r0 + ty + i * 8) * C + c0 + tx];
    __syncthreads();
    #pragma unroll
    for (int i = 0; i < 4; i++)
        Dp[(size_t)(c0 + ty + i * 8) * R + r0 + tx] = __float2half_rn(tile[tx][ty + i * 8]);
}

// finish gating: logits, top-2, softmax
__global__ void gate_kernel(const float* __restrict__ gw, const float* __restrict__ gb,
                            float* __restrict__ out_logits) {
    __shared__ float pooled[D_];
    __shared__ float logits[E_];
    const int b = blockIdx.x, d = threadIdx.x;
    float s = 0.f;
    #pragma unroll
    for (int c = 0; c < 8; c++) s += g_pool[b][c][d];
    pooled[d] = s * (1.0f / (float)T_);
    __syncthreads();
    const int w = threadIdx.x >> 5, lane = threadIdx.x & 31;
    if (w < E_) {
        float acc = 0.f;
        for (int j = lane; j < D_; j += 32) acc += pooled[j] * gw[(size_t)j * E_ + w];
        #pragma unroll
        for (int o = 16; o > 0; o >>= 1) acc += __shfl_xor_sync(0xffffffffu, acc, o);
        if (lane == 0) logits[w] = acc + gb[w];
    }
    __syncthreads();
    if (threadIdx.x == 0) {
        int i0 = 0; float l0 = logits[0];
        for (int e = 1; e < E_; e++) if (logits[e] > l0) { l0 = logits[e]; i0 = e; }
        int i1 = -1; float l1 = -1e30f;
        for (int e = 0; e < E_; e++) if (e != i0 && logits[e] > l1) { l1 = logits[e]; i1 = e; }
        float e1 = expf(l1 - l0);
        float inv = 1.0f / (1.0f + e1);
        g_eidx[b][0] = i0; g_eidx[b][1] = i1;
        g_prob[b][0] = inv; g_prob[b][1] = e1 * inv;
        for (int e = 0; e < E_; e++) out_logits[b * E_ + e] = logits[e];
    }
}

// ---------------------------------------------------------------------------
// GEMM core: 256 threads, 8 warps 2(m)x4(n), warp tile 64x32, fp16 m16n8k16
// A smem [BM][RSTR] halves (k contiguous); B smem [BN][RSTR] (k contiguous)
// ---------------------------------------------------------------------------

// each thread issues 2 A-chunks + 2 B-chunks (16B each) per stage
#define ISSUE_STAGE(slot, A_SRC, B_SRC) do {                                   \
    const uint32_t _as = sm_base + (slot) * STAGE_BYTES;                       \
    const uint32_t _bs = _as + A_BYTES;                                        \
    _Pragma("unroll")                                                          \
    for (int _i = 0; _i < 2; _i++) {                                           \
        const int _c = _i * 256 + tid;                                         \
        const int _r = _c >> 2, _cc = _c & 3;                                  \
        cp16(_as + _r * (RSTR * 2) + _cc * 16, (A_SRC(_r, _cc)));              \
    }                                                                          \
    _Pragma("unroll")                                                          \
    for (int _i = 0; _i < 2; _i++) {                                           \
        const int _c = _i * 256 + tid;                                         \
        const int _r = _c >> 2, _cc = _c & 3;                                  \
        cp16(_bs + _r * (RSTR * 2) + _cc * 16, (B_SRC(_r, _cc)));              \
    }                                                                          \
} while (0)

#define COMPUTE_STAGE(slot) do {                                               \
    const uint32_t* _A = (const uint32_t*)(smem + (slot) * STAGE_BYTES);       \
    const uint32_t* _B = (const uint32_t*)(smem + (slot) * STAGE_BYTES + A_BYTES); \
    _Pragma("unroll")                                                          \
    for (int ks = 0; ks < 2; ks++) {                                           \
        unsigned af[4][4], bf[4][2];                                           \
        _Pragma("unroll")                                                      \
        for (int mt = 0; mt < 4; mt++) {                                       \
            const int m = wm + mt * 16 + g;                                    \
            af[mt][0] = _A[m * 20 + ks * 8 + t4];                              \
            af[mt][1] = _A[(m + 8) * 20 + ks * 8 + t4];                        \
            af[mt][2] = _A[m * 20 + ks * 8 + t4 + 4];                          \
            af[mt][3] = _A[(m + 8) * 20 + ks * 8 + t4 + 4];                    \
        }                                                                      \
        _Pragma("unroll")                                                      \
        for (int nt = 0; nt < 4; nt++) {                                       \
            const int n = wn + nt * 8 + g;                                     \
            bf[nt][0] = _B[n * 20 + ks * 8 + t4];                              \
            bf[nt][1] = _B[n * 20 + ks * 8 + t4 + 4];                          \
        }                                                                      \
        _Pragma("unroll")                                                      \
        for (int mt = 0; mt < 4; mt++)                                         \
            _Pragma("unroll")                                                  \
            for (int nt = 0; nt < 4; nt++)                                     \
                mma_f16(acc[mt][nt], af[mt], bf[nt]);                          \
    }                                                                          \
} while (0)

#define GEMM_PIPELINE(NK, A_SRC, B_SRC) do {                                   \
    _Pragma("unroll")                                                          \
    for (int s = 0; s < STAGES - 1; s++) {                                     \
        const int kk = s;                                                      \
        ISSUE_STAGE(s, A_SRC, B_SRC);                                          \
        cp_commit();                                                           \
    }                                                                          \
    for (int kt = 0; kt < (NK); kt++) {                                        \
        cp_wait<STAGES - 2>();                                                 \
        __syncthreads();                                                       \
        const int pf = kt + STAGES - 1;                                        \
        if (pf < (NK)) {                                                       \
            const int kk = pf;                                                 \
            ISSUE_STAGE(pf % STAGES, A_SRC, B_SRC);                            \
        }                                                                      \
        cp_commit();                                                           \
        COMPUTE_STAGE(kt % STAGES);                                            \
    }                                                                          \
} while (0)

// ---------------------------------------------------------------------------
// GEMM1: h[b][t][slot*H + n] = fp16( p * silu( xh[b] @ w1t[e]^T + b1[e] ) )
// A: g_xh[b] [T, D];  B: g_w1t[e] [H, D]  (both k=D contiguous)
// grid (H/BN=16, T/BM=8, B*2=64)
// ---------------------------------------------------------------------------
__global__ __launch_bounds__(256, 2) void gemm1_kernel(const float* __restrict__ b1) {
    extern __shared__ char smem[];
    const uint32_t sm_base = smem_u32(smem);

    const int bz = blockIdx.z, b = bz >> 1, slot = bz & 1;
    const int e = g_eidx[b][slot];
    const float p = g_prob[b][slot];
    const int m0 = blockIdx.y * BM;
    const int n0 = blockIdx.x * BN;
    const int tid  = threadIdx.x;
    const int warp = tid >> 5, lane = tid & 31;
    const int g = lane >> 2, t4 = lane & 3;
    const int wm = (warp & 1) * 64;
    const int wn = (warp >> 1) * 32;

    const __half* Ag = g_xh  + ((size_t)b * T_ + m0) * D_;
    const __half* Bg = g_w1t + ((size_t)e * H_ + n0) * D_;

    float acc[4][4][4];
    #pragma unroll
    for (int i = 0; i < 4; i++)
        #pragma unroll
        for (int j = 0; j < 4; j++)
            #pragma unroll
            for (int r = 0; r < 4; r++) acc[i][j][r] = 0.f;

    #define A1(r, c) (Ag + (size_t)(r) * D_ + kk * BK + (c) * 8)
    #define B1(r, c) (Bg + (size_t)(r) * D_ + kk * BK + (c) * 8)
    GEMM_PIPELINE(D_ / BK, A1, B1);      // 16 k-tiles
    #undef A1
    #undef B1

    // epilogue: +b1, silu, *p, fp16, write h
    const float* brow = b1 + (size_t)e * H_ + n0;
    __half* Hb = g_h + ((size_t)b * T_ + m0) * (2 * H_) + (size_t)slot * H_ + n0;
    #pragma unroll
    for (int mt = 0; mt < 4; mt++) {
        #pragma unroll
        for (int nt = 0; nt < 4; nt++) {
            #pragma unroll
            for (int half = 0; half < 2; half++) {
                const int row = wm + mt * 16 + g + half * 8;
                const int col = wn + nt * 8 + t4 * 2;
                float v0 = acc[mt][nt][half * 2 + 0] + brow[col];
                float v1 = acc[mt][nt][half * 2 + 1] + brow[col + 1];
                v0 = p * v0 * (1.0f / (1.0f + __expf(-v0)));
                v1 = p * v1 * (1.0f / (1.0f + __expf(-v1)));
                *(__half2*)&Hb[(size_t)row * (2 * H_) + col] =
                    __floats2half2_rn(v0, v1);
            }
        }
    }
}

// ---------------------------------------------------------------------------
// GEMM2: out[b] = h_cat[b] @ [w2t[e0]; w2t[e1]]^T + p0*b2[e0] + p1*b2[e1] + x[b]
// A: g_h[b] [T, 2H] (k contiguous);  B: g_w2t[e] [D, H] (k contiguous)
// grid (D/BN=4, T/BM=8, B=32)
// ---------------------------------------------------------------------------
__global__ __launch_bounds__(256, 2) void gemm2_kernel(const float* __restrict__ x,
                                                       const float* __restrict__ b2,
                                                       float* __restrict__ out) {
    extern __shared__ char smem[];
    const uint32_t sm_base = smem_u32(smem);

    const int b = blockIdx.z;
    const int e0 = g_eidx[b][0], e1 = g_eidx[b][1];
    const float p0 = g_prob[b][0], p1 = g_prob[b][1];
    const int m0 = blockIdx.y * BM;
    const int n0 = blockIdx.x * BN;
    const int tid  = threadIdx.x;
    const int warp = tid >> 5, lane = tid & 31;
    const int g = lane >> 2, t4 = lane & 3;
    const int wm = (warp & 1) * 64;
    const int wn = (warp >> 1) * 32;

    const __half* Ag  = g_h + ((size_t)b * T_ + m0) * (2 * H_);
    const __half* Bg0 = g_w2t + ((size_t)e0 * D_ + n0) * H_;
    const __half* Bg1 = g_w2t + ((size_t)e1 * D_ + n0) * H_;

    float acc[4][4][4];
    #pragma unroll
    for (int i = 0; i < 4; i++)
        #pragma unroll
        for (int j = 0; j < 4; j++)
            #pragma unroll
            for (int r = 0; r < 4; r++) acc[i][j][r] = 0.f;

    #define A2(r, c) (Ag + (size_t)(r) * (2 * H_) + kk * BK + (c) * 8)
    #define B2(r, c) ((kk < 64 ? Bg0 : Bg1) + (size_t)(r) * H_ + (kk & 63) * BK + (c) * 8)
    GEMM_PIPELINE((2 * H_) / BK, A2, B2);    // 128 k-tiles
    #undef A2
    #undef B2

    // epilogue: + p0*b2[e0] + p1*b2[e1] + x, write out (fp32)
    const float* b2r0 = b2 + (size_t)e0 * D_ + n0;
    const float* b2r1 = b2 + (size_t)e1 * D_ + n0;
    const float* xb = x   + ((size_t)b * T_ + m0) * D_ + n0;
    float*       ob = out + ((size_t)b * T_ + m0) * D_ + n0;
    #pragma unroll
    for (int mt = 0; mt < 4; mt++) {
        #pragma unroll
        for (int nt = 0; nt < 4; nt++) {
            #pragma unroll
            for (int half = 0; half < 2; half++) {
                const int row = wm + mt * 16 + g + half * 8;
                const int col = wn + nt * 8 + t4 * 2;
                const float bias0 = p0 * b2r0[col]     + p1 * b2r1[col];
                const float bias1 = p0 * b2r0[col + 1] + p1 * b2r1[col + 1];
                const float2 xv = *(const float2*)&xb[(size_t)row * D_ + col];
                float v0 = acc[mt][nt][half * 2 + 0] + bias0 + xv.x;
                float v1 = acc[mt][nt][half * 2 + 1] + bias1 + xv.y;
                *(float2*)&ob[(size_t)row * D_ + col] = make_float2(v0, v1);
            }
        }
    }
}

// ---------------------------------------------------------------------------
extern "C" void kernel_launch(void* const* d_in, const int* in_sizes, int n_in,
                              void* d_out, int out_size) {
    const float* x  = (const float*)d_in[0];
    const float* gw = (const float*)d_in[1];
    const float* gb = (const float*)d_in[2];
    const float* w1 = (const float*)d_in[3];
    const float* b1 = (const float*)d_in[4];
    const float* w2 = (const float*)d_in[5];
    const float* b2 = (const float*)d_in[6];

    float* out = (float*)d_out;
    float* out_logits = out + (size_t)B_ * T_ * D_;

    cudaFuncSetAttribute(gemm1_kernel, cudaFuncAttributeMaxDynamicSharedMemorySize, SMEMSZ);
    cudaFuncSetAttribute(gemm2_kernel, cudaFuncAttributeMaxDynamicSharedMemorySize, SMEMSZ);

    // prep: pooling + fp16 copies/transposes
    pool_convert_kernel<<<dim3(B_, 8), 512>>>(x);
    {
        __half* w1t_ptr; cudaGetSymbolAddress((void**)&w1t_ptr, g_w1t);
        __half* w2t_ptr; cudaGetSymbolAddress((void**)&w2t_ptr, g_w2t);
        // w1 [E][D][H] -> w1t [E][H][D]
        transpose_rc_kernel<<<dim3(H_ / 32, D_ / 32, E_), dim3(32, 8)>>>(w1, w1t_ptr, D_, H_);
        // w2 [E][H][D] -> w2t [E][D][H]
        transpose_rc_kernel<<<dim3(D_ / 32, H_ / 32, E_), dim3(32, 8)>>>(w2, w2t_ptr, H_, D_);
    }
    gate_kernel<<<B_, 512>>>(gw, gb, out_logits);

    gemm1_kernel<<<dim3(H_ / BN, T_ / BM, B_ * 2), 256, SMEMSZ>>>(b1);
    gemm2_kernel<<<dim3(D_ / BN, T_ / BM, B_), 256, SMEMSZ>>>(x, b2, out);
}